// round 11
// baseline (speedup 1.0000x reference)
#include <cuda_runtime.h>

// out[b] = sum_k x[b,k] * S[k],  S[k] = sum_h W[h,k]   (scale 0.5*2.0 == 1.0)
// Both passes have the SAME proven streaming shape:
//   grid (4 k-chunks x 256 row-groups), 16 rows/CTA, front-batched MLP=8,
//   inner loop = LDG + FMA only (S held in 4 registers, not smem/L2).

#define BATCH 4096
#define IN    4096
#define HID   4096

__device__ __align__(16) float g_S[IN];

// Column-sum of W [HID, IN]. grid=(4, 256), block=256, 16 rows per CTA.
__global__ void __launch_bounds__(256, 4) colsum_kernel(const float* __restrict__ W) {
    int k4 = blockIdx.x * blockDim.x + threadIdx.x;   // float4 index along k
    int h0 = blockIdx.y * 16;

    const float4* Wv = reinterpret_cast<const float4*>(W);
    const int stride4 = IN / 4;
    long base = (long)h0 * stride4 + k4;

    float4 acc = make_float4(0.f, 0.f, 0.f, 0.f);
    #pragma unroll
    for (int g = 0; g < 2; g++) {
        float4 v[8];
        #pragma unroll
        for (int r = 0; r < 8; r++)
            v[r] = __ldcs(&Wv[base + (long)(g * 8 + r) * stride4]);
        #pragma unroll
        for (int r = 0; r < 8; r++) {
            acc.x += v[r].x; acc.y += v[r].y; acc.z += v[r].z; acc.w += v[r].w;
        }
    }
    float* dst = &g_S[k4 * 4];
    asm volatile("red.global.add.v4.f32 [%0], {%1, %2, %3, %4};"
                 :: "l"(dst), "f"(acc.x), "f"(acc.y), "f"(acc.z), "f"(acc.w)
                 : "memory");
}

// Matvec with colsum's exact streaming shape. Each thread owns ONE float4
// column position (S in 4 registers), iterates 16 rows, partials to smem,
// deferred reduce, REDG accumulate into out (4 chunk-updates per row).
__global__ void __launch_bounds__(256, 4) matvec_kernel(const float* __restrict__ x,
                                                        float* __restrict__ out) {
    __shared__ float part[16][257];       // +1 pad

    const int tid  = threadIdx.x;
    const int lane = tid & 31;
    const int wid  = tid >> 5;

    int k4 = blockIdx.x * blockDim.x + tid;   // float4 column index
    int r0 = blockIdx.y * 16;                 // first row of this CTA

    const float4 s4 = reinterpret_cast<const float4*>(g_S)[k4];  // once, L2-hot
    const float4* xv = reinterpret_cast<const float4*>(x);
    const int stride4 = IN / 4;
    long base = (long)r0 * stride4 + k4;

    // Phase A: pure streaming (LDG.128 + 4 FMA + STS.32), no barriers.
    #pragma unroll
    for (int g = 0; g < 2; g++) {
        float4 v[8];
        #pragma unroll
        for (int r = 0; r < 8; r++)
            v[r] = __ldcs(&xv[base + (long)(g * 8 + r) * stride4]);
        #pragma unroll
        for (int r = 0; r < 8; r++) {
            float p = fmaf(v[r].x, s4.x,
                      fmaf(v[r].y, s4.y,
                      fmaf(v[r].z, s4.z, v[r].w * s4.w)));
            part[g * 8 + r][tid] = p;     // thread owns its slot
        }
    }
    __syncthreads();

    // Phase B: warp w reduces rows w and w+8; REDG into out[row].
    #pragma unroll
    for (int rr = 0; rr < 2; rr++) {
        int r = wid + rr * 8;
        float s = 0.f;
        #pragma unroll
        for (int j = 0; j < 8; j++)
            s += part[r][lane + j * 32];
        #pragma unroll
        for (int off = 16; off > 0; off >>= 1)
            s += __shfl_xor_sync(0xFFFFFFFFu, s, off);
        if (lane == 0)
            asm volatile("red.global.add.f32 [%0], %1;"
                         :: "l"(&out[r0 + r]), "f"(s) : "memory");
    }
}

extern "C" void kernel_launch(void* const* d_in, const int* in_sizes, int n_in,
                              void* d_out, int out_size) {
    const float* x = (const float*)d_in[0];
    const float* W = (const float*)d_in[1];
    float* out = (float*)d_out;

    void* s_ptr = nullptr;
    cudaGetSymbolAddress(&s_ptr, g_S);
    cudaMemsetAsync(s_ptr, 0, IN * sizeof(float));
    cudaMemsetAsync(out, 0, BATCH * sizeof(float));

    dim3 grid(IN / (256 * 4), HID / 16);
    colsum_kernel<<<grid, 256>>>(W);
    matvec_kernel<<<grid, 256>>>(x, out);
}